// round 12
// baseline (speedup 1.0000x reference)
#include <cuda_runtime.h>
#include <cuda_fp16.h>
#include <cstdint>
#include <cstddef>

// ---------------------------------------------------------------------------
// DeepFM on GB300 — round 12: hybrid grid strategy.
//  GEMM1 (1024 tiles, 3.5 waves): one tile per CTA  -> natural overlap.
//  GEMM2/3 (512/256 tiles, bad tails): persistent 2xSM grid.
// Kernel body = R10 (persistent loop, no cross-tile pipeline — it was neutral).
// ---------------------------------------------------------------------------

#define NROWS 16384
#define FDIM  39
#define VDIM  50000
#define EDIM  64
#define KDEEP (FDIM * EDIM)   // 2496
#define C1 1024
#define C2 512
#define C3 256
#define BN_EPS 1e-5f
#define NBLK (NROWS / 128)

// ----------------- scratch -----------------
__device__ __align__(1024) __half g_deep[(size_t)NROWS * KDEEP];
__device__ __align__(1024) __half g_z[(size_t)NROWS * C1];
__device__ __align__(1024) __half g_h[(size_t)NROWS * C1];
__device__ __align__(1024) __half g_bt[(size_t)KDEEP * C1];        // (C x K)
__device__ float  g_psumf[NBLK * C1];
__device__ float  g_psqf [NBLK * C1];
__device__ float  g_scale[C1];
__device__ float  g_shift[C1];
__device__ int    g_idx64;

// ----------------- PTX helpers -----------------
__device__ __forceinline__ uint32_t smem_u32(const void* p) {
    uint32_t a;
    asm("{ .reg .u64 t; cvta.to.shared.u64 t, %1; cvt.u32.u64 %0, t; }" : "=r"(a) : "l"(p));
    return a;
}
#define CP_ASYNC16(dst, src) asm volatile("cp.async.cg.shared.global [%0], [%1], 16;" :: "r"(dst), "l"(src))
#define CP_COMMIT()          asm volatile("cp.async.commit_group;" ::: "memory")
#define CP_WAIT(n)           asm volatile("cp.async.wait_group %0;" :: "n"(n) : "memory")

__device__ __forceinline__ void ldsm_x4(uint32_t* r, uint32_t addr) {
    asm volatile("ldmatrix.sync.aligned.m8n8.x4.shared.b16 {%0,%1,%2,%3}, [%4];"
                 : "=r"(r[0]), "=r"(r[1]), "=r"(r[2]), "=r"(r[3]) : "r"(addr));
}
__device__ __forceinline__ void mma_f16(float* c, const uint32_t* a, const uint32_t* b) {
    asm volatile("mma.sync.aligned.m16n8k16.row.col.f32.f16.f16.f32 "
                 "{%0,%1,%2,%3}, {%4,%5,%6,%7}, {%8,%9}, {%0,%1,%2,%3};"
                 : "+f"(c[0]), "+f"(c[1]), "+f"(c[2]), "+f"(c[3])
                 : "r"(a[0]), "r"(a[1]), "r"(a[2]), "r"(a[3]), "r"(b[0]), "r"(b[1]));
}
__device__ __forceinline__ uint32_t pack2h(__half a, __half b) {
    return (uint32_t)__half_as_ushort(a) | ((uint32_t)__half_as_ushort(b) << 16);
}

// ----------------- 0. Xi dtype detection -----------------
__global__ void detect_idx_kernel(const unsigned int* xi_words) {
    unsigned int acc = 0;
    for (int i = 1; i < 64; i += 2) acc |= xi_words[i];
    g_idx64 = (acc == 0) ? 1 : 0;
}

// ----------------- 1. embed + FM -----------------
__global__ void embed_kernel(const void* __restrict__ Xi_raw,
                             const float* __restrict__ Xv,
                             const float* __restrict__ W1,
                             const float* __restrict__ W2,
                             const float* __restrict__ bias,
                             float* __restrict__ out) {
    const int tx = threadIdx.x, ty = threadIdx.y;
    const int n  = blockIdx.x * 4 + ty;
    const bool is64 = (g_idx64 != 0);
    const long long* Xi64 = (const long long*)Xi_raw;
    const int*       Xi32 = (const int*)Xi_raw;

    float s = 0.f, sq = 0.f;
    #pragma unroll
    for (int f = 0; f < FDIM; ++f) {
        int idx = is64 ? (int)Xi64[(size_t)n * FDIM + f] : Xi32[(size_t)n * FDIM + f];
        float xv = Xv[(size_t)n * FDIM + f];
        float w  = W2[((size_t)f * VDIM + idx) * EDIM + tx] * xv;
        g_deep[(size_t)n * KDEEP + f * EDIM + tx] = __float2half(w);
        s += w; sq += w * w;
    }
    float v = 0.5f * (s * s - sq);
    if (tx < FDIM) {
        int idx = is64 ? (int)Xi64[(size_t)n * FDIM + tx] : Xi32[(size_t)n * FDIM + tx];
        v += W1[(size_t)tx * VDIM + idx] * Xv[(size_t)n * FDIM + tx];
    }
    #pragma unroll
    for (int off = 16; off > 0; off >>= 1) v += __shfl_down_sync(0xffffffffu, v, off);
    __shared__ float red[4][2];
    if ((tx & 31) == 0) red[ty][tx >> 5] = v;
    __syncthreads();
    if (tx == 0) out[n] = red[ty][0] + red[ty][1] + bias[0];
}

// ----------------- 2. weight prep -----------------
__global__ void prep_wt_kernel(const float* __restrict__ W,
                               __half* __restrict__ Bt, int K, int C) {
    __shared__ float t[32][33];
    const int c0 = blockIdx.x * 32, k0 = blockIdx.y * 32;
    #pragma unroll
    for (int r = threadIdx.y; r < 32; r += 8)
        t[r][threadIdx.x] = W[(size_t)(k0 + r) * C + c0 + threadIdx.x];
    __syncthreads();
    #pragma unroll
    for (int r = threadIdx.y; r < 32; r += 8)
        Bt[(size_t)(c0 + r) * K + k0 + threadIdx.x] = __float2half(t[threadIdx.x][r]);
}

// ----------------- 3. FP16 HMMA GEMM + fused BN stats ----------
#define BM 128
#define BNT 128
#define BKC 64
#define ROWB 128
#define A_BYTES (BM * ROWB)
#define B_BYTES (BNT * ROWB)
#define OFF_A 0
#define OFF_B (A_BYTES)
#define STAGE_BYTES (A_BYTES + B_BYTES)     // 32768
#define NSTAGE 3
#define GEMM_SMEM (NSTAGE * STAGE_BYTES)    // 98304

__global__ void __launch_bounds__(128, 2)
gemmh_kernel(const __half* __restrict__ Ag, const __half* __restrict__ Bg,
             const float* __restrict__ bias, __half* __restrict__ Z,
             int K, int Nc, int tiles_n, int ntiles) {
    extern __shared__ __align__(1024) char smem[];
    const uint32_t sb = smem_u32(smem);
    const int tid = threadIdx.x, wid = tid >> 5, lane = tid & 31;
    const int wm = wid & 1, wn = wid >> 1;           // 2m x 2n

    // ---- loader addressing (tile-invariant)
    const int r0 = tid >> 3, ch = tid & 7;
    const uint32_t cxor   = ((uint32_t)(ch * 16)) ^ ((uint32_t)(r0 & 7) * 16);
    const uint32_t adst0  = OFF_A + (uint32_t)r0 * ROWB + cxor;   // + q*2048
    const uint32_t bdst0  = OFF_B + (uint32_t)r0 * ROWB + cxor;
    const size_t   srcoff = (size_t)r0 * K + ch * 8;              // + q*16*K
    const size_t   K16    = (size_t)16 * K;

    // ---- ldmatrix addressing (tile-invariant)
    const uint32_t a_row  = (uint32_t)(wm * 64 + (lane & 15));
    const uint32_t a_colb = (uint32_t)((lane >> 4) * 16);
    const uint32_t b_row  = (uint32_t)(wn * 64 + ((lane >> 4) & 1) * 8 + (lane & 7));
    const uint32_t b_colb = (uint32_t)(((lane >> 3) & 1) * 16);
    uint32_t axor[4], bxor[4];
    #pragma unroll
    for (int ks = 0; ks < 4; ++ks) {
        axor[ks] = ((uint32_t)(ks * 32) + a_colb) ^ ((a_row & 7) * 16);
        bxor[ks] = ((uint32_t)(ks * 32) + b_colb) ^ ((b_row & 7) * 16);
    }
    const uint32_t a_base = OFF_A + a_row * ROWB;
    const uint32_t b_base = OFF_B + b_row * ROWB;

    const int nc = K / BKC;

    for (int t = blockIdx.x; t < ntiles; t += gridDim.x) {
        const int bx = t % tiles_n, by = t / tiles_n;
        const int m0 = by * BM, n0 = bx * BNT;
        const __half* asrc = Ag + (size_t)m0 * K + srcoff;
        const __half* bsrc = Bg + (size_t)n0 * K + srcoff;

        float acc[4][8][4];
        #pragma unroll
        for (int i = 0; i < 4; ++i)
            #pragma unroll
            for (int j = 0; j < 8; ++j)
                #pragma unroll
                for (int q = 0; q < 4; ++q) acc[i][j][q] = 0.f;

        // prologue: 2 stages
        #pragma unroll
        for (int s = 0; s < 2; ++s) {
            const uint32_t st = sb + (uint32_t)s * STAGE_BYTES;
            #pragma unroll
            for (int q = 0; q < 8; ++q) {
                CP_ASYNC16(st + adst0 + q * 2048, asrc + s * BKC + q * K16);
                CP_ASYNC16(st + bdst0 + q * 2048, bsrc + s * BKC + q * K16);
            }
            CP_COMMIT();
        }

        uint32_t afr[2][4][4], bfr[2][8][2];

        for (int i = 0; i < nc; ++i) {
            CP_WAIT(1);
            __syncthreads();
            {
                const int j = i + 2;
                if (j < nc) {
                    const uint32_t st = sb + (uint32_t)(j % NSTAGE) * STAGE_BYTES;
                    #pragma unroll
                    for (int q = 0; q < 8; ++q) {
                        CP_ASYNC16(st + adst0 + q * 2048, asrc + j * BKC + q * K16);
                        CP_ASYNC16(st + bdst0 + q * 2048, bsrc + j * BKC + q * K16);
                    }
                }
                CP_COMMIT();
            }
            const uint32_t st = sb + (uint32_t)(i % NSTAGE) * STAGE_BYTES;

            #pragma unroll
            for (int mt = 0; mt < 4; ++mt)
                ldsm_x4(afr[0][mt], st + a_base + mt * 2048 + axor[0]);
            #pragma unroll
            for (int p = 0; p < 4; ++p) {
                uint32_t tt[4];
                ldsm_x4(tt, st + b_base + p * 2048 + bxor[0]);
                bfr[0][2*p][0] = tt[0]; bfr[0][2*p][1] = tt[1];
                bfr[0][2*p+1][0] = tt[2]; bfr[0][2*p+1][1] = tt[3];
            }

            #pragma unroll
            for (int ks = 0; ks < 4; ++ks) {
                const int cur = ks & 1, nxt = cur ^ 1;
                if (ks < 3) {
                    #pragma unroll
                    for (int mt = 0; mt < 4; ++mt)
                        ldsm_x4(afr[nxt][mt], st + a_base + mt * 2048 + axor[ks + 1]);
                    #pragma unroll
                    for (int p = 0; p < 4; ++p) {
                        uint32_t tt[4];
                        ldsm_x4(tt, st + b_base + p * 2048 + bxor[ks + 1]);
                        bfr[nxt][2*p][0] = tt[0]; bfr[nxt][2*p][1] = tt[1];
                        bfr[nxt][2*p+1][0] = tt[2]; bfr[nxt][2*p+1][1] = tt[3];
                    }
                }
                #pragma unroll
                for (int mt = 0; mt < 4; ++mt)
                    #pragma unroll
                    for (int nt = 0; nt < 8; ++nt)
                        mma_f16(acc[mt][nt], afr[cur][mt], bfr[cur][nt]);
            }
        }

        // ---------- epilogue: fp16 z + per-tile BN partial stats ----------
        __syncthreads();
        float* colsum = (float*)smem;
        float* colsq  = (float*)smem + 128;
        colsum[tid] = 0.f; colsq[tid] = 0.f;
        __syncthreads();

        #pragma unroll
        for (int nt = 0; nt < 8; ++nt) {
            const int cloc = wn * 64 + nt * 8 + (lane & 3) * 2;
            const int col  = n0 + cloc;
            const float b0 = bias[col], b1 = bias[col + 1];
            float s0 = 0.f, s1 = 0.f, q0 = 0.f, q1 = 0.f;
            #pragma unroll
            for (int mt = 0; mt < 4; ++mt) {
                const int row = m0 + wm * 64 + mt * 16 + (lane >> 2);
                float z00 = acc[mt][nt][0] + b0, z01 = acc[mt][nt][1] + b1;
                float z10 = acc[mt][nt][2] + b0, z11 = acc[mt][nt][3] + b1;
                s0 += z00 + z10;  s1 += z01 + z11;
                q0 += z00 * z00 + z10 * z10;  q1 += z01 * z01 + z11 * z11;
                *(uint32_t*)&Z[(size_t)row * Nc + col]       = pack2h(__float2half(z00), __float2half(z01));
                *(uint32_t*)&Z[(size_t)(row + 8) * Nc + col] = pack2h(__float2half(z10), __float2half(z11));
            }
            #pragma unroll
            for (int off = 16; off >= 4; off >>= 1) {
                s0 += __shfl_down_sync(0xffffffffu, s0, off);
                s1 += __shfl_down_sync(0xffffffffu, s1, off);
                q0 += __shfl_down_sync(0xffffffffu, q0, off);
                q1 += __shfl_down_sync(0xffffffffu, q1, off);
            }
            if ((lane >> 2) == 0) {
                atomicAdd(&colsum[cloc], s0);     atomicAdd(&colsum[cloc + 1], s1);
                atomicAdd(&colsq[cloc],  q0);     atomicAdd(&colsq[cloc + 1],  q1);
            }
        }
        __syncthreads();
        g_psumf[(size_t)by * Nc + n0 + tid] = colsum[tid];
        g_psqf [(size_t)by * Nc + n0 + tid] = colsq[tid];
        __syncthreads();   // protect colsum/colsq (overlaps stage 0) from next tile's cp.async
    }
}

// ----------------- 4. BN finalize / apply -----------------
__global__ void bn_finalize_kernel(const float* __restrict__ g,
                                   const float* __restrict__ b, int C) {
    const int col = blockIdx.x * blockDim.x + threadIdx.x;
    if (col >= C) return;
    double s = 0.0, ss = 0.0;
    for (int i = 0; i < NBLK; ++i) { s += g_psumf[i * C + col]; ss += g_psqf[i * C + col]; }
    double mean = s / (double)NROWS;
    double var  = ss / (double)NROWS - mean * mean;
    float sc = g[col] * rsqrtf((float)var + BN_EPS);
    g_scale[col] = sc;
    g_shift[col] = b[col] - (float)mean * sc;
}

__global__ void bn_apply_kernel(const uint4* __restrict__ z,
                                uint4* __restrict__ h,
                                size_t total8, int cmask) {
    const size_t stride = (size_t)gridDim.x * blockDim.x;
    for (size_t t = (size_t)blockIdx.x * blockDim.x + threadIdx.x; t < total8; t += stride) {
        const size_t i = t * 8;
        const int col = (int)(i & (size_t)cmask);
        uint4 zin = z[t];
        const __half2* zp = (const __half2*)&zin;
        float4 s0 = *(const float4*)(g_scale + col);
        float4 s1 = *(const float4*)(g_scale + col + 4);
        float4 f0 = *(const float4*)(g_shift + col);
        float4 f1 = *(const float4*)(g_shift + col + 4);
        float2 p0 = __half22float2(zp[0]);
        float2 p1 = __half22float2(zp[1]);
        float2 p2 = __half22float2(zp[2]);
        float2 p3 = __half22float2(zp[3]);
        float v0 = fmaxf(fmaf(p0.x, s0.x, f0.x), 0.f), v1 = fmaxf(fmaf(p0.y, s0.y, f0.y), 0.f);
        float v2 = fmaxf(fmaf(p1.x, s0.z, f0.z), 0.f), v3 = fmaxf(fmaf(p1.y, s0.w, f0.w), 0.f);
        float v4 = fmaxf(fmaf(p2.x, s1.x, f1.x), 0.f), v5 = fmaxf(fmaf(p2.y, s1.y, f1.y), 0.f);
        float v6 = fmaxf(fmaf(p3.x, s1.z, f1.z), 0.f), v7 = fmaxf(fmaf(p3.y, s1.w, f1.w), 0.f);
        uint4 u;
        u.x = pack2h(__float2half(v0), __float2half(v1));
        u.y = pack2h(__float2half(v2), __float2half(v3));
        u.z = pack2h(__float2half(v4), __float2half(v5));
        u.w = pack2h(__float2half(v6), __float2half(v7));
        h[t] = u;
    }
}

// ----------------- 5. fused layer-3 BN + ReLU + row-sum -----------------
__global__ void rowsum_bn_kernel(const __half* __restrict__ z, float* __restrict__ out) {
    const int gwarp = (blockIdx.x * blockDim.x + threadIdx.x) >> 5;
    const int lane  = threadIdx.x & 31;
    if (gwarp >= NROWS) return;
    const __half2* p = (const __half2*)(z + (size_t)gwarp * C3);
    float s = 0.f;
    #pragma unroll
    for (int j = 0; j < C3 / 64; ++j) {
        const int c2 = lane + j * 32;
        float2 v = __half22float2(p[c2]);
        s += fmaxf(fmaf(v.x, g_scale[2 * c2], g_shift[2 * c2]), 0.f);
        s += fmaxf(fmaf(v.y, g_scale[2 * c2 + 1], g_shift[2 * c2 + 1]), 0.f);
    }
    #pragma unroll
    for (int off = 16; off > 0; off >>= 1) s += __shfl_down_sync(0xffffffffu, s, off);
    if (lane == 0) out[gwarp] += s;
}

// ---------------------------------------------------------------------------
extern "C" void kernel_launch(void* const* d_in, const int* in_sizes, int n_in,
                              void* d_out, int out_size) {
    const void*  Xi   = d_in[0];
    const float* Xv   = (const float*)d_in[1];
    const float* W1   = (const float*)d_in[2];
    const float* W2   = (const float*)d_in[3];
    const float* bias = (const float*)d_in[4];
    const float* lw1  = (const float*)d_in[5];
    const float* lb1  = (const float*)d_in[6];
    const float* g1   = (const float*)d_in[7];
    const float* b1   = (const float*)d_in[8];
    const float* lw2  = (const float*)d_in[9];
    const float* lb2  = (const float*)d_in[10];
    const float* g2   = (const float*)d_in[11];
    const float* b2   = (const float*)d_in[12];
    const float* lw3  = (const float*)d_in[13];
    const float* lb3  = (const float*)d_in[14];
    const float* g3   = (const float*)d_in[15];
    const float* b3   = (const float*)d_in[16];
    float* out = (float*)d_out;

    __half *deep, *h, *bt, *z;
    cudaGetSymbolAddress((void**)&deep, g_deep);
    cudaGetSymbolAddress((void**)&h,    g_h);
    cudaGetSymbolAddress((void**)&bt,   g_bt);
    cudaGetSymbolAddress((void**)&z,    g_z);

    static int nsm = 0;
    if (nsm == 0) {
        cudaDeviceGetAttribute(&nsm, cudaDevAttrMultiProcessorCount, 0);
        if (nsm <= 0) nsm = 148;
        cudaFuncSetAttribute(gemmh_kernel, cudaFuncAttributeMaxDynamicSharedMemorySize, GEMM_SMEM);
    }
    const int P = 2 * nsm;

    detect_idx_kernel<<<1, 1>>>((const unsigned int*)Xi);

    dim3 ebt(64, 4);
    embed_kernel<<<NROWS / 4, ebt>>>(Xi, Xv, W1, W2, bias, out);

    // ---- layer 1: 2496 -> 1024 (many tiles: one tile per CTA) ----
    {
        prep_wt_kernel<<<dim3(C1 / 32, KDEEP / 32), dim3(32, 8)>>>(lw1, bt, KDEEP, C1);
        const int tn = C1 / BNT, nt = tn * (NROWS / BM);   // 1024 tiles
        gemmh_kernel<<<nt, 128, GEMM_SMEM>>>(deep, bt, lb1, z, KDEEP, C1, tn, nt);
        bn_finalize_kernel<<<(C1 + 255) / 256, 256>>>(g1, b1, C1);
        bn_apply_kernel<<<1024, 256>>>((const uint4*)z, (uint4*)h, (size_t)NROWS * C1 / 8, C1 - 1);
    }
    // ---- layer 2: 1024 -> 512 (1.73 waves: persistent grid) ----
    {
        prep_wt_kernel<<<dim3(C2 / 32, C1 / 32), dim3(32, 8)>>>(lw2, bt, C1, C2);
        const int tn = C2 / BNT, nt = tn * (NROWS / BM);   // 512 tiles
        gemmh_kernel<<<(nt < P ? nt : P), 128, GEMM_SMEM>>>(h, bt, lb2, z, C1, C2, tn, nt);
        bn_finalize_kernel<<<(C2 + 255) / 256, 256>>>(g2, b2, C2);
        bn_apply_kernel<<<1024, 256>>>((const uint4*)z, (uint4*)h, (size_t)NROWS * C2 / 8, C2 - 1);
    }
    // ---- layer 3: 512 -> 256 (0.86 waves: persistent grid; BN+rowsum fused) ----
    {
        prep_wt_kernel<<<dim3(C3 / 32, C2 / 32), dim3(32, 8)>>>(lw3, bt, C2, C3);
        const int tn = C3 / BNT, nt = tn * (NROWS / BM);   // 256 tiles
        gemmh_kernel<<<(nt < P ? nt : P), 128, GEMM_SMEM>>>(h, bt, lb3, z, C2, C3, tn, nt);
        bn_finalize_kernel<<<(C3 + 255) / 256, 256>>>(g3, b3, C3);
        rowsum_bn_kernel<<<(NROWS * 32 + 255) / 256, 256>>>(z, out);
    }
}

// round 13
// speedup vs baseline: 1.0235x; 1.0235x over previous
#include <cuda_runtime.h>
#include <cuda_fp16.h>
#include <cstdint>
#include <cstddef>

// ---------------------------------------------------------------------------
// DeepFM on GB300 — round 13: BN+ReLU fused into consumer GEMM A-fragments
// (half2 hfma2/hmax2 on ldmatrix output). bn_apply kernels + h buffer gone.
// GEMM core unchanged from R12 (warp 64x64, CTA 128x128, BK=64+SW128,
// 2 CTAs/SM; GEMM1 one-tile-per-CTA, GEMM2/3 persistent).
// ---------------------------------------------------------------------------

#define NROWS 16384
#define FDIM  39
#define VDIM  50000
#define EDIM  64
#define KDEEP (FDIM * EDIM)   // 2496
#define C1 1024
#define C2 512
#define C3 256
#define BN_EPS 1e-5f
#define NBLK (NROWS / 128)

// ----------------- scratch -----------------
__device__ __align__(1024) __half g_deep[(size_t)NROWS * KDEEP];
__device__ __align__(1024) __half g_zA[(size_t)NROWS * C1];   // layer1 out, layer3 out
__device__ __align__(1024) __half g_zB[(size_t)NROWS * C2];   // layer2 out
__device__ __align__(1024) __half g_bt[(size_t)KDEEP * C1];   // (C x K) weights
__device__ float  g_psumf[NBLK * C1];
__device__ float  g_psqf [NBLK * C1];
__device__ float  g_scale[C1];
__device__ float  g_shift[C1];
__device__ __half g_sc2[C1];     // fp16 scale (read as half2)
__device__ __half g_sh2[C1];     // fp16 shift
__device__ int    g_idx64;

// ----------------- PTX helpers -----------------
__device__ __forceinline__ uint32_t smem_u32(const void* p) {
    uint32_t a;
    asm("{ .reg .u64 t; cvta.to.shared.u64 t, %1; cvt.u32.u64 %0, t; }" : "=r"(a) : "l"(p));
    return a;
}
#define CP_ASYNC16(dst, src) asm volatile("cp.async.cg.shared.global [%0], [%1], 16;" :: "r"(dst), "l"(src))
#define CP_COMMIT()          asm volatile("cp.async.commit_group;" ::: "memory")
#define CP_WAIT(n)           asm volatile("cp.async.wait_group %0;" :: "n"(n) : "memory")

__device__ __forceinline__ void ldsm_x4(uint32_t* r, uint32_t addr) {
    asm volatile("ldmatrix.sync.aligned.m8n8.x4.shared.b16 {%0,%1,%2,%3}, [%4];"
                 : "=r"(r[0]), "=r"(r[1]), "=r"(r[2]), "=r"(r[3]) : "r"(addr));
}
__device__ __forceinline__ void mma_f16(float* c, const uint32_t* a, const uint32_t* b) {
    asm volatile("mma.sync.aligned.m16n8k16.row.col.f32.f16.f16.f32 "
                 "{%0,%1,%2,%3}, {%4,%5,%6,%7}, {%8,%9}, {%0,%1,%2,%3};"
                 : "+f"(c[0]), "+f"(c[1]), "+f"(c[2]), "+f"(c[3])
                 : "r"(a[0]), "r"(a[1]), "r"(a[2]), "r"(a[3]), "r"(b[0]), "r"(b[1]));
}
__device__ __forceinline__ uint32_t pack2h(__half a, __half b) {
    return (uint32_t)__half_as_ushort(a) | ((uint32_t)__half_as_ushort(b) << 16);
}
__device__ __forceinline__ uint32_t bnrelu2(uint32_t v, __half2 sc, __half2 sh) {
    __half2 x = __hfma2(*(__half2*)&v, sc, sh);
    x = __hmax2(x, __float2half2_rn(0.f));
    return *(uint32_t*)&x;
}

// ----------------- 0. Xi dtype detection -----------------
__global__ void detect_idx_kernel(const unsigned int* xi_words) {
    unsigned int acc = 0;
    for (int i = 1; i < 64; i += 2) acc |= xi_words[i];
    g_idx64 = (acc == 0) ? 1 : 0;
}

// ----------------- 1. embed + FM -----------------
__global__ void embed_kernel(const void* __restrict__ Xi_raw,
                             const float* __restrict__ Xv,
                             const float* __restrict__ W1,
                             const float* __restrict__ W2,
                             const float* __restrict__ bias,
                             float* __restrict__ out) {
    const int tx = threadIdx.x, ty = threadIdx.y;
    const int n  = blockIdx.x * 4 + ty;
    const bool is64 = (g_idx64 != 0);
    const long long* Xi64 = (const long long*)Xi_raw;
    const int*       Xi32 = (const int*)Xi_raw;

    float s = 0.f, sq = 0.f;
    #pragma unroll
    for (int f = 0; f < FDIM; ++f) {
        int idx = is64 ? (int)Xi64[(size_t)n * FDIM + f] : Xi32[(size_t)n * FDIM + f];
        float xv = Xv[(size_t)n * FDIM + f];
        float w  = W2[((size_t)f * VDIM + idx) * EDIM + tx] * xv;
        g_deep[(size_t)n * KDEEP + f * EDIM + tx] = __float2half(w);
        s += w; sq += w * w;
    }
    float v = 0.5f * (s * s - sq);
    if (tx < FDIM) {
        int idx = is64 ? (int)Xi64[(size_t)n * FDIM + tx] : Xi32[(size_t)n * FDIM + tx];
        v += W1[(size_t)tx * VDIM + idx] * Xv[(size_t)n * FDIM + tx];
    }
    #pragma unroll
    for (int off = 16; off > 0; off >>= 1) v += __shfl_down_sync(0xffffffffu, v, off);
    __shared__ float red[4][2];
    if ((tx & 31) == 0) red[ty][tx >> 5] = v;
    __syncthreads();
    if (tx == 0) out[n] = red[ty][0] + red[ty][1] + bias[0];
}

// ----------------- 2. weight prep -----------------
__global__ void prep_wt_kernel(const float* __restrict__ W,
                               __half* __restrict__ Bt, int K, int C) {
    __shared__ float t[32][33];
    const int c0 = blockIdx.x * 32, k0 = blockIdx.y * 32;
    #pragma unroll
    for (int r = threadIdx.y; r < 32; r += 8)
        t[r][threadIdx.x] = W[(size_t)(k0 + r) * C + c0 + threadIdx.x];
    __syncthreads();
    #pragma unroll
    for (int r = threadIdx.y; r < 32; r += 8)
        Bt[(size_t)(c0 + r) * K + k0 + threadIdx.x] = __float2half(t[threadIdx.x][r]);
}

// ----------------- 3. FP16 HMMA GEMM + fused BN stats (+optional BN on A) --
#define BM 128
#define BNT 128
#define BKC 64
#define ROWB 128
#define A_BYTES (BM * ROWB)
#define B_BYTES (BNT * ROWB)
#define OFF_A 0
#define OFF_B (A_BYTES)
#define STAGE_BYTES (A_BYTES + B_BYTES)     // 32768
#define NSTAGE 3
#define GEMM_SMEM (NSTAGE * STAGE_BYTES)    // 98304

template<bool BN>
__global__ void __launch_bounds__(128, 2)
gemmh_kernel(const __half* __restrict__ Ag, const __half* __restrict__ Bg,
             const float* __restrict__ bias, __half* __restrict__ Z,
             int K, int Nc, int tiles_n, int ntiles) {
    extern __shared__ __align__(1024) char smem[];
    const uint32_t sb = smem_u32(smem);
    const int tid = threadIdx.x, wid = tid >> 5, lane = tid & 31;
    const int wm = wid & 1, wn = wid >> 1;           // 2m x 2n

    // ---- loader addressing (tile-invariant)
    const int r0 = tid >> 3, ch = tid & 7;
    const uint32_t cxor   = ((uint32_t)(ch * 16)) ^ ((uint32_t)(r0 & 7) * 16);
    const uint32_t adst0  = OFF_A + (uint32_t)r0 * ROWB + cxor;   // + q*2048
    const uint32_t bdst0  = OFF_B + (uint32_t)r0 * ROWB + cxor;
    const size_t   srcoff = (size_t)r0 * K + ch * 8;              // + q*16*K
    const size_t   K16    = (size_t)16 * K;

    // ---- ldmatrix addressing (tile-invariant)
    const uint32_t a_row  = (uint32_t)(wm * 64 + (lane & 15));
    const uint32_t a_colb = (uint32_t)((lane >> 4) * 16);
    const uint32_t b_row  = (uint32_t)(wn * 64 + ((lane >> 4) & 1) * 8 + (lane & 7));
    const uint32_t b_colb = (uint32_t)(((lane >> 3) & 1) * 16);
    uint32_t axor[4], bxor[4];
    #pragma unroll
    for (int ks = 0; ks < 4; ++ks) {
        axor[ks] = ((uint32_t)(ks * 32) + a_colb) ^ ((a_row & 7) * 16);
        bxor[ks] = ((uint32_t)(ks * 32) + b_colb) ^ ((b_row & 7) * 16);
    }
    const uint32_t a_base = OFF_A + a_row * ROWB;
    const uint32_t b_base = OFF_B + b_row * ROWB;
    const int kp0 = lane & 3;                       // BN pair base within ks

    const __half2* sc2 = (const __half2*)g_sc2;
    const __half2* sh2 = (const __half2*)g_sh2;

    const int nc = K / BKC;

    for (int t = blockIdx.x; t < ntiles; t += gridDim.x) {
        const int bx = t % tiles_n, by = t / tiles_n;
        const int m0 = by * BM, n0 = bx * BNT;
        const __half* asrc = Ag + (size_t)m0 * K + srcoff;
        const __half* bsrc = Bg + (size_t)n0 * K + srcoff;

        float acc[4][8][4];
        #pragma unroll
        for (int i = 0; i < 4; ++i)
            #pragma unroll
            for (int j = 0; j < 8; ++j)
                #pragma unroll
                for (int q = 0; q < 4; ++q) acc[i][j][q] = 0.f;

        #pragma unroll
        for (int s = 0; s < 2; ++s) {
            const uint32_t st = sb + (uint32_t)s * STAGE_BYTES;
            #pragma unroll
            for (int q = 0; q < 8; ++q) {
                CP_ASYNC16(st + adst0 + q * 2048, asrc + s * BKC + q * K16);
                CP_ASYNC16(st + bdst0 + q * 2048, bsrc + s * BKC + q * K16);
            }
            CP_COMMIT();
        }

        uint32_t afr[2][4][4], bfr[2][8][2];

        for (int i = 0; i < nc; ++i) {
            CP_WAIT(1);
            __syncthreads();
            {
                const int j = i + 2;
                if (j < nc) {
                    const uint32_t st = sb + (uint32_t)(j % NSTAGE) * STAGE_BYTES;
                    #pragma unroll
                    for (int q = 0; q < 8; ++q) {
                        CP_ASYNC16(st + adst0 + q * 2048, asrc + j * BKC + q * K16);
                        CP_ASYNC16(st + bdst0 + q * 2048, bsrc + j * BKC + q * K16);
                    }
                }
                CP_COMMIT();
            }
            const uint32_t st = sb + (uint32_t)(i % NSTAGE) * STAGE_BYTES;
            const int kpi = i * 32 + kp0;           // BN pair base for this chunk

            // preload ks=0
            #pragma unroll
            for (int mt = 0; mt < 4; ++mt)
                ldsm_x4(afr[0][mt], st + a_base + mt * 2048 + axor[0]);
            if (BN) {
                const __half2 s0 = sc2[kpi],     h0 = sh2[kpi];
                const __half2 s1 = sc2[kpi + 4], h1 = sh2[kpi + 4];
                #pragma unroll
                for (int mt = 0; mt < 4; ++mt) {
                    afr[0][mt][0] = bnrelu2(afr[0][mt][0], s0, h0);
                    afr[0][mt][1] = bnrelu2(afr[0][mt][1], s0, h0);
                    afr[0][mt][2] = bnrelu2(afr[0][mt][2], s1, h1);
                    afr[0][mt][3] = bnrelu2(afr[0][mt][3], s1, h1);
                }
            }
            #pragma unroll
            for (int p = 0; p < 4; ++p) {
                uint32_t tt[4];
                ldsm_x4(tt, st + b_base + p * 2048 + bxor[0]);
                bfr[0][2*p][0] = tt[0]; bfr[0][2*p][1] = tt[1];
                bfr[0][2*p+1][0] = tt[2]; bfr[0][2*p+1][1] = tt[3];
            }

            #pragma unroll
            for (int ks = 0; ks < 4; ++ks) {
                const int cur = ks & 1, nxt = cur ^ 1;
                if (ks < 3) {
                    #pragma unroll
                    for (int mt = 0; mt < 4; ++mt)
                        ldsm_x4(afr[nxt][mt], st + a_base + mt * 2048 + axor[ks + 1]);
                    if (BN) {
                        const int kp = kpi + (ks + 1) * 8;
                        const __half2 s0 = sc2[kp],     h0 = sh2[kp];
                        const __half2 s1 = sc2[kp + 4], h1 = sh2[kp + 4];
                        #pragma unroll
                        for (int mt = 0; mt < 4; ++mt) {
                            afr[nxt][mt][0] = bnrelu2(afr[nxt][mt][0], s0, h0);
                            afr[nxt][mt][1] = bnrelu2(afr[nxt][mt][1], s0, h0);
                            afr[nxt][mt][2] = bnrelu2(afr[nxt][mt][2], s1, h1);
                            afr[nxt][mt][3] = bnrelu2(afr[nxt][mt][3], s1, h1);
                        }
                    }
                    #pragma unroll
                    for (int p = 0; p < 4; ++p) {
                        uint32_t tt[4];
                        ldsm_x4(tt, st + b_base + p * 2048 + bxor[ks + 1]);
                        bfr[nxt][2*p][0] = tt[0]; bfr[nxt][2*p][1] = tt[1];
                        bfr[nxt][2*p+1][0] = tt[2]; bfr[nxt][2*p+1][1] = tt[3];
                    }
                }
                #pragma unroll
                for (int mt = 0; mt < 4; ++mt)
                    #pragma unroll
                    for (int nt = 0; nt < 8; ++nt)
                        mma_f16(acc[mt][nt], afr[cur][mt], bfr[cur][nt]);
            }
        }

        // ---------- epilogue: fp16 z + per-tile BN partial stats ----------
        __syncthreads();
        float* colsum = (float*)smem;
        float* colsq  = (float*)smem + 128;
        colsum[tid] = 0.f; colsq[tid] = 0.f;
        __syncthreads();

        #pragma unroll
        for (int nt = 0; nt < 8; ++nt) {
            const int cloc = wn * 64 + nt * 8 + (lane & 3) * 2;
            const int col  = n0 + cloc;
            const float b0 = bias[col], b1 = bias[col + 1];
            float s0 = 0.f, s1 = 0.f, q0 = 0.f, q1 = 0.f;
            #pragma unroll
            for (int mt = 0; mt < 4; ++mt) {
                const int row = m0 + wm * 64 + mt * 16 + (lane >> 2);
                float z00 = acc[mt][nt][0] + b0, z01 = acc[mt][nt][1] + b1;
                float z10 = acc[mt][nt][2] + b0, z11 = acc[mt][nt][3] + b1;
                s0 += z00 + z10;  s1 += z01 + z11;
                q0 += z00 * z00 + z10 * z10;  q1 += z01 * z01 + z11 * z11;
                *(uint32_t*)&Z[(size_t)row * Nc + col]       = pack2h(__float2half(z00), __float2half(z01));
                *(uint32_t*)&Z[(size_t)(row + 8) * Nc + col] = pack2h(__float2half(z10), __float2half(z11));
            }
            #pragma unroll
            for (int off = 16; off >= 4; off >>= 1) {
                s0 += __shfl_down_sync(0xffffffffu, s0, off);
                s1 += __shfl_down_sync(0xffffffffu, s1, off);
                q0 += __shfl_down_sync(0xffffffffu, q0, off);
                q1 += __shfl_down_sync(0xffffffffu, q1, off);
            }
            if ((lane >> 2) == 0) {
                atomicAdd(&colsum[cloc], s0);     atomicAdd(&colsum[cloc + 1], s1);
                atomicAdd(&colsq[cloc],  q0);     atomicAdd(&colsq[cloc + 1],  q1);
            }
        }
        __syncthreads();
        g_psumf[(size_t)by * Nc + n0 + tid] = colsum[tid];
        g_psqf [(size_t)by * Nc + n0 + tid] = colsq[tid];
        __syncthreads();
    }
}

// ----------------- 4. BN finalize (fp32 + packed fp16) -----------------
__global__ void bn_finalize_kernel(const float* __restrict__ g,
                                   const float* __restrict__ b, int C) {
    const int col = blockIdx.x * blockDim.x + threadIdx.x;
    if (col >= C) return;
    double s = 0.0, ss = 0.0;
    for (int i = 0; i < NBLK; ++i) { s += g_psumf[i * C + col]; ss += g_psqf[i * C + col]; }
    double mean = s / (double)NROWS;
    double var  = ss / (double)NROWS - mean * mean;
    float sc = g[col] * rsqrtf((float)var + BN_EPS);
    float sh = b[col] - (float)mean * sc;
    g_scale[col] = sc;
    g_shift[col] = sh;
    g_sc2[col] = __float2half(sc);
    g_sh2[col] = __float2half(sh);
}

// ----------------- 5. fused layer-3 BN + ReLU + row-sum -----------------
__global__ void rowsum_bn_kernel(const __half* __restrict__ z, float* __restrict__ out) {
    const int gwarp = (blockIdx.x * blockDim.x + threadIdx.x) >> 5;
    const int lane  = threadIdx.x & 31;
    if (gwarp >= NROWS) return;
    const __half2* p = (const __half2*)(z + (size_t)gwarp * C3);
    float s = 0.f;
    #pragma unroll
    for (int j = 0; j < C3 / 64; ++j) {
        const int c2 = lane + j * 32;
        float2 v = __half22float2(p[c2]);
        s += fmaxf(fmaf(v.x, g_scale[2 * c2], g_shift[2 * c2]), 0.f);
        s += fmaxf(fmaf(v.y, g_scale[2 * c2 + 1], g_shift[2 * c2 + 1]), 0.f);
    }
    #pragma unroll
    for (int off = 16; off > 0; off >>= 1) s += __shfl_down_sync(0xffffffffu, s, off);
    if (lane == 0) out[gwarp] += s;
}

// ---------------------------------------------------------------------------
extern "C" void kernel_launch(void* const* d_in, const int* in_sizes, int n_in,
                              void* d_out, int out_size) {
    const void*  Xi   = d_in[0];
    const float* Xv   = (const float*)d_in[1];
    const float* W1   = (const float*)d_in[2];
    const float* W2   = (const float*)d_in[3];
    const float* bias = (const float*)d_in[4];
    const float* lw1  = (const float*)d_in[5];
    const float* lb1  = (const float*)d_in[6];
    const float* g1   = (const float*)d_in[7];
    const float* b1   = (const float*)d_in[8];
    const float* lw2  = (const float*)d_in[9];
    const float* lb2  = (const float*)d_in[10];
    const float* g2   = (const float*)d_in[11];
    const float* b2   = (const float*)d_in[12];
    const float* lw3  = (const float*)d_in[13];
    const float* lb3  = (const float*)d_in[14];
    const float* g3   = (const float*)d_in[15];
    const float* b3   = (const float*)d_in[16];
    float* out = (float*)d_out;

    __half *deep, *zA, *zB, *bt;
    cudaGetSymbolAddress((void**)&deep, g_deep);
    cudaGetSymbolAddress((void**)&zA,   g_zA);
    cudaGetSymbolAddress((void**)&zB,   g_zB);
    cudaGetSymbolAddress((void**)&bt,   g_bt);

    static int nsm = 0;
    if (nsm == 0) {
        cudaDeviceGetAttribute(&nsm, cudaDevAttrMultiProcessorCount, 0);
        if (nsm <= 0) nsm = 148;
        cudaFuncSetAttribute(gemmh_kernel<false>, cudaFuncAttributeMaxDynamicSharedMemorySize, GEMM_SMEM);
        cudaFuncSetAttribute(gemmh_kernel<true>,  cudaFuncAttributeMaxDynamicSharedMemorySize, GEMM_SMEM);
    }
    const int P = 2 * nsm;

    detect_idx_kernel<<<1, 1>>>((const unsigned int*)Xi);

    dim3 ebt(64, 4);
    embed_kernel<<<NROWS / 4, ebt>>>(Xi, Xv, W1, W2, bias, out);

    // ---- layer 1: 2496 -> 1024 (deep -> zA; no BN on input) ----
    {
        prep_wt_kernel<<<dim3(C1 / 32, KDEEP / 32), dim3(32, 8)>>>(lw1, bt, KDEEP, C1);
        const int tn = C1 / BNT, nt = tn * (NROWS / BM);   // 1024 tiles: 1 tile/CTA
        gemmh_kernel<false><<<nt, 128, GEMM_SMEM>>>(deep, bt, lb1, zA, KDEEP, C1, tn, nt);
        bn_finalize_kernel<<<(C1 + 255) / 256, 256>>>(g1, b1, C1);
    }
    // ---- layer 2: 1024 -> 512 (zA -> zB; BN+ReLU fused on A) ----
    {
        prep_wt_kernel<<<dim3(C2 / 32, C1 / 32), dim3(32, 8)>>>(lw2, bt, C1, C2);
        const int tn = C2 / BNT, nt = tn * (NROWS / BM);   // 512 tiles: persistent
        gemmh_kernel<true><<<(nt < P ? nt : P), 128, GEMM_SMEM>>>(zA, bt, lb2, zB, C1, C2, tn, nt);
        bn_finalize_kernel<<<(C2 + 255) / 256, 256>>>(g2, b2, C2);
    }
    // ---- layer 3: 512 -> 256 (zB -> zA; BN+ReLU fused on A) ----
    {
        prep_wt_kernel<<<dim3(C3 / 32, C2 / 32), dim3(32, 8)>>>(lw3, bt, C2, C3);
        const int tn = C3 / BNT, nt = tn * (NROWS / BM);   // 256 tiles: persistent
        gemmh_kernel<true><<<(nt < P ? nt : P), 128, GEMM_SMEM>>>(zB, bt, lb3, zA, C2, C3, tn, nt);
        bn_finalize_kernel<<<(C3 + 255) / 256, 256>>>(g3, b3, C3);
    }
    rowsum_bn_kernel<<<(NROWS * 32 + 255) / 256, 256>>>(zA, out);
}

// round 15
// speedup vs baseline: 1.0447x; 1.0207x over previous
#include <cuda_runtime.h>
#include <cuda_fp16.h>
#include <cstdint>
#include <cstddef>

// ---------------------------------------------------------------------------
// DeepFM on GB300 — round 15: R14 with the dtype-probe OOB fixed.
//  * inline dtype detection now probes the FIRST 16 words of Xi (in-bounds
//    for both int32 and int64 buffers) instead of per-block offsets.
//  * prep_wt x3 still overlapped with embed on a forked side stream.
//  GEMM core unchanged: warp 64x64, CTA 128x128, BK=64+SW128, 2 CTAs/SM,
//  BN+ReLU fused into A-fragments for layers 2/3.
// ---------------------------------------------------------------------------

#define NROWS 16384
#define FDIM  39
#define VDIM  50000
#define EDIM  64
#define KDEEP (FDIM * EDIM)   // 2496
#define C1 1024
#define C2 512
#define C3 256
#define BN_EPS 1e-5f
#define NBLK (NROWS / 128)

// ----------------- scratch -----------------
__device__ __align__(1024) __half g_deep[(size_t)NROWS * KDEEP];
__device__ __align__(1024) __half g_zA[(size_t)NROWS * C1];
__device__ __align__(1024) __half g_zB[(size_t)NROWS * C2];
__device__ __align__(1024) __half g_bt1[(size_t)KDEEP * C1];
__device__ __align__(1024) __half g_bt2[(size_t)C1 * C2];
__device__ __align__(1024) __half g_bt3[(size_t)C2 * C3];
__device__ float  g_psumf[NBLK * C1];
__device__ float  g_psqf [NBLK * C1];
__device__ float  g_scale[C1];
__device__ float  g_shift[C1];
__device__ __half g_sc2[C1];
__device__ __half g_sh2[C1];

// ----------------- PTX helpers -----------------
__device__ __forceinline__ uint32_t smem_u32(const void* p) {
    uint32_t a;
    asm("{ .reg .u64 t; cvta.to.shared.u64 t, %1; cvt.u32.u64 %0, t; }" : "=r"(a) : "l"(p));
    return a;
}
#define CP_ASYNC16(dst, src) asm volatile("cp.async.cg.shared.global [%0], [%1], 16;" :: "r"(dst), "l"(src))
#define CP_COMMIT()          asm volatile("cp.async.commit_group;" ::: "memory")
#define CP_WAIT(n)           asm volatile("cp.async.wait_group %0;" :: "n"(n) : "memory")

__device__ __forceinline__ void ldsm_x4(uint32_t* r, uint32_t addr) {
    asm volatile("ldmatrix.sync.aligned.m8n8.x4.shared.b16 {%0,%1,%2,%3}, [%4];"
                 : "=r"(r[0]), "=r"(r[1]), "=r"(r[2]), "=r"(r[3]) : "r"(addr));
}
__device__ __forceinline__ void mma_f16(float* c, const uint32_t* a, const uint32_t* b) {
    asm volatile("mma.sync.aligned.m16n8k16.row.col.f32.f16.f16.f32 "
                 "{%0,%1,%2,%3}, {%4,%5,%6,%7}, {%8,%9}, {%0,%1,%2,%3};"
                 : "+f"(c[0]), "+f"(c[1]), "+f"(c[2]), "+f"(c[3])
                 : "r"(a[0]), "r"(a[1]), "r"(a[2]), "r"(a[3]), "r"(b[0]), "r"(b[1]));
}
__device__ __forceinline__ uint32_t pack2h(__half a, __half b) {
    return (uint32_t)__half_as_ushort(a) | ((uint32_t)__half_as_ushort(b) << 16);
}
__device__ __forceinline__ uint32_t bnrelu2(uint32_t v, __half2 sc, __half2 sh) {
    __half2 x = __hfma2(*(__half2*)&v, sc, sh);
    x = __hmax2(x, __float2half2_rn(0.f));
    return *(uint32_t*)&x;
}

// ----------------- 1. embed + FM (safe inline dtype detection) -------------
__global__ void embed_kernel(const void* __restrict__ Xi_raw,
                             const float* __restrict__ Xv,
                             const float* __restrict__ W1,
                             const float* __restrict__ W2,
                             const float* __restrict__ bias,
                             float* __restrict__ out) {
    const int tx = threadIdx.x, ty = threadIdx.y;
    const int n  = blockIdx.x * 4 + ty;
    const long long* Xi64 = (const long long*)Xi_raw;
    const int*       Xi32 = (const int*)Xi_raw;

    // dtype detection: probe FIRST 16 words of Xi (256 B — in-bounds for both
    // int32 [2.5 MB] and int64 [5.1 MB] buffers; L2-cached). For int64 values
    // < 2^31 every odd word is 0; for 8 random int32 indices P(all zero)~1e-37.
    __shared__ int sh_is64;
    if (tx == 0 && ty == 0) {
        const unsigned int* w = (const unsigned int*)Xi_raw;
        unsigned int acc = 0;
        #pragma unroll
        for (int i = 1; i < 16; i += 2) acc |= w[i];
        sh_is64 = (acc == 0) ? 1 : 0;
    }
    __syncthreads();
    const bool is64 = (sh_is64 != 0);

    float s = 0.f, sq = 0.f;
    #pragma unroll
    for (int f = 0; f < FDIM; ++f) {
        int idx = is64 ? (int)Xi64[(size_t)n * FDIM + f] : Xi32[(size_t)n * FDIM + f];
        float xv = Xv[(size_t)n * FDIM + f];
        float w  = W2[((size_t)f * VDIM + idx) * EDIM + tx] * xv;
        g_deep[(size_t)n * KDEEP + f * EDIM + tx] = __float2half(w);
        s += w; sq += w * w;
    }
    float v = 0.5f * (s * s - sq);
    if (tx < FDIM) {
        int idx = is64 ? (int)Xi64[(size_t)n * FDIM + tx] : Xi32[(size_t)n * FDIM + tx];
        v += W1[(size_t)tx * VDIM + idx] * Xv[(size_t)n * FDIM + tx];
    }
    #pragma unroll
    for (int off = 16; off > 0; off >>= 1) v += __shfl_down_sync(0xffffffffu, v, off);
    __shared__ float red[4][2];
    if ((tx & 31) == 0) red[ty][tx >> 5] = v;
    __syncthreads();
    if (tx == 0) out[n] = red[ty][0] + red[ty][1] + bias[0];
}

// ----------------- 2. weight prep -----------------
__global__ void prep_wt_kernel(const float* __restrict__ W,
                               __half* __restrict__ Bt, int K, int C) {
    __shared__ float t[32][33];
    const int c0 = blockIdx.x * 32, k0 = blockIdx.y * 32;
    #pragma unroll
    for (int r = threadIdx.y; r < 32; r += 8)
        t[r][threadIdx.x] = W[(size_t)(k0 + r) * C + c0 + threadIdx.x];
    __syncthreads();
    #pragma unroll
    for (int r = threadIdx.y; r < 32; r += 8)
        Bt[(size_t)(c0 + r) * K + k0 + threadIdx.x] = __float2half(t[threadIdx.x][r]);
}

// ----------------- 3. FP16 HMMA GEMM + fused BN stats (+optional BN on A) --
#define BM 128
#define BNT 128
#define BKC 64
#define ROWB 128
#define A_BYTES (BM * ROWB)
#define B_BYTES (BNT * ROWB)
#define OFF_A 0
#define OFF_B (A_BYTES)
#define STAGE_BYTES (A_BYTES + B_BYTES)     // 32768
#define NSTAGE 3
#define GEMM_SMEM (NSTAGE * STAGE_BYTES)    // 98304

template<bool BN>
__global__ void __launch_bounds__(128, 2)
gemmh_kernel(const __half* __restrict__ Ag, const __half* __restrict__ Bg,
             const float* __restrict__ bias, __half* __restrict__ Z,
             int K, int Nc, int tiles_n, int ntiles) {
    extern __shared__ __align__(1024) char smem[];
    const uint32_t sb = smem_u32(smem);
    const int tid = threadIdx.x, wid = tid >> 5, lane = tid & 31;
    const int wm = wid & 1, wn = wid >> 1;

    const int r0 = tid >> 3, ch = tid & 7;
    const uint32_t cxor   = ((uint32_t)(ch * 16)) ^ ((uint32_t)(r0 & 7) * 16);
    const uint32_t adst0  = OFF_A + (uint32_t)r0 * ROWB + cxor;
    const uint32_t bdst0  = OFF_B + (uint32_t)r0 * ROWB + cxor;
    const size_t   srcoff = (size_t)r0 * K + ch * 8;
    const size_t   K16    = (size_t)16 * K;

    const uint32_t a_row  = (uint32_t)(wm * 64 + (lane & 15));
    const uint32_t a_colb = (uint32_t)((lane >> 4) * 16);
    const uint32_t b_row  = (uint32_t)(wn * 64 + ((lane >> 4) & 1) * 8 + (lane & 7));
    const uint32_t b_colb = (uint32_t)(((lane >> 3) & 1) * 16);
    uint32_t axor[4], bxor[4];
    #pragma unroll
    for (int ks = 0; ks < 4; ++ks) {
        axor[ks] = ((uint32_t)(ks * 32) + a_colb) ^ ((a_row & 7) * 16);
        bxor[ks] = ((uint32_t)(ks * 32) + b_colb) ^ ((b_row & 7) * 16);
    }
    const uint32_t a_base = OFF_A + a_row * ROWB;
    const uint32_t b_base = OFF_B + b_row * ROWB;
    const int kp0 = lane & 3;

    const __half2* sc2 = (const __half2*)g_sc2;
    const __half2* sh2 = (const __half2*)g_sh2;

    const int nc = K / BKC;

    for (int t = blockIdx.x; t < ntiles; t += gridDim.x) {
        const int bx = t % tiles_n, by = t / tiles_n;
        const int m0 = by * BM, n0 = bx * BNT;
        const __half* asrc = Ag + (size_t)m0 * K + srcoff;
        const __half* bsrc = Bg + (size_t)n0 * K + srcoff;

        float acc[4][8][4];
        #pragma unroll
        for (int i = 0; i < 4; ++i)
            #pragma unroll
            for (int j = 0; j < 8; ++j)
                #pragma unroll
                for (int q = 0; q < 4; ++q) acc[i][j][q] = 0.f;

        #pragma unroll
        for (int s = 0; s < 2; ++s) {
            const uint32_t st = sb + (uint32_t)s * STAGE_BYTES;
            #pragma unroll
            for (int q = 0; q < 8; ++q) {
                CP_ASYNC16(st + adst0 + q * 2048, asrc + s * BKC + q * K16);
                CP_ASYNC16(st + bdst0 + q * 2048, bsrc + s * BKC + q * K16);
            }
            CP_COMMIT();
        }

        uint32_t afr[2][4][4], bfr[2][8][2];

        for (int i = 0; i < nc; ++i) {
            CP_WAIT(1);
            __syncthreads();
            {
                const int j = i + 2;
                if (j < nc) {
                    const uint32_t st = sb + (uint32_t)(j % NSTAGE) * STAGE_BYTES;
                    #pragma unroll
                    for (int q = 0; q < 8; ++q) {
                        CP_ASYNC16(st + adst0 + q * 2048, asrc + j * BKC + q * K16);
                        CP_ASYNC16(st + bdst0 + q * 2048, bsrc + j * BKC + q * K16);
                    }
                }
                CP_COMMIT();
            }
            const uint32_t st = sb + (uint32_t)(i % NSTAGE) * STAGE_BYTES;
            const int kpi = i * 32 + kp0;

            #pragma unroll
            for (int mt = 0; mt < 4; ++mt)
                ldsm_x4(afr[0][mt], st + a_base + mt * 2048 + axor[0]);
            if (BN) {
                const __half2 s0 = sc2[kpi],     h0 = sh2[kpi];
                const __half2 s1 = sc2[kpi + 4], h1 = sh2[kpi + 4];
                #pragma unroll
                for (int mt = 0; mt < 4; ++mt) {
                    afr[0][mt][0] = bnrelu2(afr[0][mt][0], s0, h0);
                    afr[0][mt][1] = bnrelu2(afr[0][mt][1], s0, h0);
                    afr[0][mt][2] = bnrelu2(afr[0][mt][2], s1, h1);
                    afr[0][mt][3] = bnrelu2(afr[0][mt][3], s1, h1);
                }
            }
            #pragma unroll
            for (int p = 0; p < 4; ++p) {
                uint32_t tt[4];
                ldsm_x4(tt, st + b_base + p * 2048 + bxor[0]);
                bfr[0][2*p][0] = tt[0]; bfr[0][2*p][1] = tt[1];
                bfr[0][2*p+1][0] = tt[2]; bfr[0][2*p+1][1] = tt[3];
            }

            #pragma unroll
            for (int ks = 0; ks < 4; ++ks) {
                const int cur = ks & 1, nxt = cur ^ 1;
                if (ks < 3) {
                    #pragma unroll
                    for (int mt = 0; mt < 4; ++mt)
                        ldsm_x4(afr[nxt][mt], st + a_base + mt * 2048 + axor[ks + 1]);
                    if (BN) {
                        const int kp = kpi + (ks + 1) * 8;
                        const __half2 s0 = sc2[kp],     h0 = sh2[kp];
                        const __half2 s1 = sc2[kp + 4], h1 = sh2[kp + 4];
                        #pragma unroll
                        for (int mt = 0; mt < 4; ++mt) {
                            afr[nxt][mt][0] = bnrelu2(afr[nxt][mt][0], s0, h0);
                            afr[nxt][mt][1] = bnrelu2(afr[nxt][mt][1], s0, h0);
                            afr[nxt][mt][2] = bnrelu2(afr[nxt][mt][2], s1, h1);
                            afr[nxt][mt][3] = bnrelu2(afr[nxt][mt][3], s1, h1);
                        }
                    }
                    #pragma unroll
                    for (int p = 0; p < 4; ++p) {
                        uint32_t tt[4];
                        ldsm_x4(tt, st + b_base + p * 2048 + bxor[ks + 1]);
                        bfr[nxt][2*p][0] = tt[0]; bfr[nxt][2*p][1] = tt[1];
                        bfr[nxt][2*p+1][0] = tt[2]; bfr[nxt][2*p+1][1] = tt[3];
                    }
                }
                #pragma unroll
                for (int mt = 0; mt < 4; ++mt)
                    #pragma unroll
                    for (int nt = 0; nt < 8; ++nt)
                        mma_f16(acc[mt][nt], afr[cur][mt], bfr[cur][nt]);
            }
        }

        // ---------- epilogue: fp16 z + per-tile BN partial stats ----------
        __syncthreads();
        float* colsum = (float*)smem;
        float* colsq  = (float*)smem + 128;
        colsum[tid] = 0.f; colsq[tid] = 0.f;
        __syncthreads();

        #pragma unroll
        for (int nt = 0; nt < 8; ++nt) {
            const int cloc = wn * 64 + nt * 8 + (lane & 3) * 2;
            const int col  = n0 + cloc;
            const float b0 = bias[col], b1 = bias[col + 1];
            float s0 = 0.f, s1 = 0.f, q0 = 0.f, q1 = 0.f;
            #pragma unroll
            for (int mt = 0; mt < 4; ++mt) {
                const int row = m0 + wm * 64 + mt * 16 + (lane >> 2);
                float z00 = acc[mt][nt][0] + b0, z01 = acc[mt][nt][1] + b1;
                float z10 = acc[mt][nt][2] + b0, z11 = acc[mt][nt][3] + b1;
                s0 += z00 + z10;  s1 += z01 + z11;
                q0 += z00 * z00 + z10 * z10;  q1 += z01 * z01 + z11 * z11;
                *(uint32_t*)&Z[(size_t)row * Nc + col]       = pack2h(__float2half(z00), __float2half(z01));
                *(uint32_t*)&Z[(size_t)(row + 8) * Nc + col] = pack2h(__float2half(z10), __float2half(z11));
            }
            #pragma unroll
            for (int off = 16; off >= 4; off >>= 1) {
                s0 += __shfl_down_sync(0xffffffffu, s0, off);
                s1 += __shfl_down_sync(0xffffffffu, s1, off);
                q0 += __shfl_down_sync(0xffffffffu, q0, off);
                q1 += __shfl_down_sync(0xffffffffu, q1, off);
            }
            if ((lane >> 2) == 0) {
                atomicAdd(&colsum[cloc], s0);     atomicAdd(&colsum[cloc + 1], s1);
                atomicAdd(&colsq[cloc],  q0);     atomicAdd(&colsq[cloc + 1],  q1);
            }
        }
        __syncthreads();
        g_psumf[(size_t)by * Nc + n0 + tid] = colsum[tid];
        g_psqf [(size_t)by * Nc + n0 + tid] = colsq[tid];
        __syncthreads();
    }
}

// ----------------- 4. BN finalize -----------------
__global__ void bn_finalize_kernel(const float* __restrict__ g,
                                   const float* __restrict__ b, int C) {
    const int col = blockIdx.x * blockDim.x + threadIdx.x;
    if (col >= C) return;
    double s = 0.0, ss = 0.0;
    for (int i = 0; i < NBLK; ++i) { s += g_psumf[i * C + col]; ss += g_psqf[i * C + col]; }
    double mean = s / (double)NROWS;
    double var  = ss / (double)NROWS - mean * mean;
    float sc = g[col] * rsqrtf((float)var + BN_EPS);
    float sh = b[col] - (float)mean * sc;
    g_scale[col] = sc;
    g_shift[col] = sh;
    g_sc2[col] = __float2half(sc);
    g_sh2[col] = __float2half(sh);
}

// ----------------- 5. fused layer-3 BN + ReLU + row-sum -----------------
__global__ void rowsum_bn_kernel(const __half* __restrict__ z, float* __restrict__ out) {
    const int gwarp = (blockIdx.x * blockDim.x + threadIdx.x) >> 5;
    const int lane  = threadIdx.x & 31;
    if (gwarp >= NROWS) return;
    const __half2* p = (const __half2*)(z + (size_t)gwarp * C3);
    float s = 0.f;
    #pragma unroll
    for (int j = 0; j < C3 / 64; ++j) {
        const int c2 = lane + j * 32;
        float2 v = __half22float2(p[c2]);
        s += fmaxf(fmaf(v.x, g_scale[2 * c2], g_shift[2 * c2]), 0.f);
        s += fmaxf(fmaf(v.y, g_scale[2 * c2 + 1], g_shift[2 * c2 + 1]), 0.f);
    }
    #pragma unroll
    for (int off = 16; off > 0; off >>= 1) s += __shfl_down_sync(0xffffffffu, s, off);
    if (lane == 0) out[gwarp] += s;
}

// ---------------------------------------------------------------------------
extern "C" void kernel_launch(void* const* d_in, const int* in_sizes, int n_in,
                              void* d_out, int out_size) {
    const void*  Xi   = d_in[0];
    const float* Xv   = (const float*)d_in[1];
    const float* W1   = (const float*)d_in[2];
    const float* W2   = (const float*)d_in[3];
    const float* bias = (const float*)d_in[4];
    const float* lw1  = (const float*)d_in[5];
    const float* lb1  = (const float*)d_in[6];
    const float* g1   = (const float*)d_in[7];
    const float* b1   = (const float*)d_in[8];
    const float* lw2  = (const float*)d_in[9];
    const float* lb2  = (const float*)d_in[10];
    const float* g2   = (const float*)d_in[11];
    const float* b2   = (const float*)d_in[12];
    const float* lw3  = (const float*)d_in[13];
    const float* lb3  = (const float*)d_in[14];
    const float* g3   = (const float*)d_in[15];
    const float* b3   = (const float*)d_in[16];
    float* out = (float*)d_out;

    __half *deep, *zA, *zB, *bt1, *bt2, *bt3;
    cudaGetSymbolAddress((void**)&deep, g_deep);
    cudaGetSymbolAddress((void**)&zA,   g_zA);
    cudaGetSymbolAddress((void**)&zB,   g_zB);
    cudaGetSymbolAddress((void**)&bt1,  g_bt1);
    cudaGetSymbolAddress((void**)&bt2,  g_bt2);
    cudaGetSymbolAddress((void**)&bt3,  g_bt3);

    static int nsm = 0;
    static cudaStream_t s2;
    static cudaEvent_t evFork, evJoin;
    if (nsm == 0) {
        cudaDeviceGetAttribute(&nsm, cudaDevAttrMultiProcessorCount, 0);
        if (nsm <= 0) nsm = 148;
        cudaFuncSetAttribute(gemmh_kernel<false>, cudaFuncAttributeMaxDynamicSharedMemorySize, GEMM_SMEM);
        cudaFuncSetAttribute(gemmh_kernel<true>,  cudaFuncAttributeMaxDynamicSharedMemorySize, GEMM_SMEM);
        cudaStreamCreateWithFlags(&s2, cudaStreamNonBlocking);
        cudaEventCreateWithFlags(&evFork, cudaEventDisableTiming);
        cudaEventCreateWithFlags(&evJoin, cudaEventDisableTiming);
    }
    const int P = 2 * nsm;

    // ---- fork: weight preps on side stream, overlapped with embed ----
    cudaEventRecord(evFork, 0);
    cudaStreamWaitEvent(s2, evFork, 0);
    prep_wt_kernel<<<dim3(C1 / 32, KDEEP / 32), dim3(32, 8), 0, s2>>>(lw1, bt1, KDEEP, C1);
    prep_wt_kernel<<<dim3(C2 / 32, C1 / 32),    dim3(32, 8), 0, s2>>>(lw2, bt2, C1, C2);
    prep_wt_kernel<<<dim3(C3 / 32, C2 / 32),    dim3(32, 8), 0, s2>>>(lw3, bt3, C2, C3);
    cudaEventRecord(evJoin, s2);

    dim3 ebt(64, 4);
    embed_kernel<<<NROWS / 4, ebt>>>(Xi, Xv, W1, W2, bias, out);

    cudaStreamWaitEvent(0, evJoin, 0);   // join before GEMM1

    // ---- layer 1: 2496 -> 1024 (deep -> zA) ----
    {
        const int tn = C1 / BNT, nt = tn * (NROWS / BM);
        gemmh_kernel<false><<<nt, 128, GEMM_SMEM>>>(deep, bt1, lb1, zA, KDEEP, C1, tn, nt);
        bn_finalize_kernel<<<(C1 + 255) / 256, 256>>>(g1, b1, C1);
    }
    // ---- layer 2: 1024 -> 512 (zA -> zB; BN+ReLU fused on A) ----
    {
        const int tn = C2 / BNT, nt = tn * (NROWS / BM);
        gemmh_kernel<true><<<(nt < P ? nt : P), 128, GEMM_SMEM>>>(zA, bt2, lb2, zB, C1, C2, tn, nt);
        bn_finalize_kernel<<<(C2 + 255) / 256, 256>>>(g2, b2, C2);
    }
    // ---- layer 3: 512 -> 256 (zB -> zA; BN+ReLU fused on A) ----
    {
        const int tn = C3 / BNT, nt = tn * (NROWS / BM);
        gemmh_kernel<true><<<(nt < P ? nt : P), 128, GEMM_SMEM>>>(zB, bt3, lb3, zA, C2, C3, tn, nt);
        bn_finalize_kernel<<<(C3 + 255) / 256, 256>>>(g3, b3, C3);
    }
    rowsum_bn_kernel<<<(NROWS * 32 + 255) / 256, 256>>>(zA, out);
}

// round 16
// speedup vs baseline: 1.3358x; 1.2787x over previous
#include <cuda_runtime.h>
#include <cuda_fp16.h>
#include <cstdint>
#include <cstddef>

// ---------------------------------------------------------------------------
// DeepFM on GB300 — round 16: parallel bn_finalize (1 block/column, 128-thread
// double-precision tree reduction) replacing the 4-block serial version that
// sat 3x on the critical path. Embed: 8 rows/block. Rest = R15.
// ---------------------------------------------------------------------------

#define NROWS 16384
#define FDIM  39
#define VDIM  50000
#define EDIM  64
#define KDEEP (FDIM * EDIM)   // 2496
#define C1 1024
#define C2 512
#define C3 256
#define BN_EPS 1e-5f
#define NBLK (NROWS / 128)    // 128

// ----------------- scratch -----------------
__device__ __align__(1024) __half g_deep[(size_t)NROWS * KDEEP];
__device__ __align__(1024) __half g_zA[(size_t)NROWS * C1];
__device__ __align__(1024) __half g_zB[(size_t)NROWS * C2];
__device__ __align__(1024) __half g_bt1[(size_t)KDEEP * C1];
__device__ __align__(1024) __half g_bt2[(size_t)C1 * C2];
__device__ __align__(1024) __half g_bt3[(size_t)C2 * C3];
__device__ float  g_psumf[NBLK * C1];
__device__ float  g_psqf [NBLK * C1];
__device__ float  g_scale[C1];
__device__ float  g_shift[C1];
__device__ __half g_sc2[C1];
__device__ __half g_sh2[C1];

// ----------------- PTX helpers -----------------
__device__ __forceinline__ uint32_t smem_u32(const void* p) {
    uint32_t a;
    asm("{ .reg .u64 t; cvta.to.shared.u64 t, %1; cvt.u32.u64 %0, t; }" : "=r"(a) : "l"(p));
    return a;
}
#define CP_ASYNC16(dst, src) asm volatile("cp.async.cg.shared.global [%0], [%1], 16;" :: "r"(dst), "l"(src))
#define CP_COMMIT()          asm volatile("cp.async.commit_group;" ::: "memory")
#define CP_WAIT(n)           asm volatile("cp.async.wait_group %0;" :: "n"(n) : "memory")

__device__ __forceinline__ void ldsm_x4(uint32_t* r, uint32_t addr) {
    asm volatile("ldmatrix.sync.aligned.m8n8.x4.shared.b16 {%0,%1,%2,%3}, [%4];"
                 : "=r"(r[0]), "=r"(r[1]), "=r"(r[2]), "=r"(r[3]) : "r"(addr));
}
__device__ __forceinline__ void mma_f16(float* c, const uint32_t* a, const uint32_t* b) {
    asm volatile("mma.sync.aligned.m16n8k16.row.col.f32.f16.f16.f32 "
                 "{%0,%1,%2,%3}, {%4,%5,%6,%7}, {%8,%9}, {%0,%1,%2,%3};"
                 : "+f"(c[0]), "+f"(c[1]), "+f"(c[2]), "+f"(c[3])
                 : "r"(a[0]), "r"(a[1]), "r"(a[2]), "r"(a[3]), "r"(b[0]), "r"(b[1]));
}
__device__ __forceinline__ uint32_t pack2h(__half a, __half b) {
    return (uint32_t)__half_as_ushort(a) | ((uint32_t)__half_as_ushort(b) << 16);
}
__device__ __forceinline__ uint32_t bnrelu2(uint32_t v, __half2 sc, __half2 sh) {
    __half2 x = __hfma2(*(__half2*)&v, sc, sh);
    x = __hmax2(x, __float2half2_rn(0.f));
    return *(uint32_t*)&x;
}

// ----------------- 1. embed + FM (8 rows/block, safe dtype probe) ----------
__global__ void embed_kernel(const void* __restrict__ Xi_raw,
                             const float* __restrict__ Xv,
                             const float* __restrict__ W1,
                             const float* __restrict__ W2,
                             const float* __restrict__ bias,
                             float* __restrict__ out) {
    const int tx = threadIdx.x, ty = threadIdx.y;
    const int n  = blockIdx.x * 8 + ty;
    const long long* Xi64 = (const long long*)Xi_raw;
    const int*       Xi32 = (const int*)Xi_raw;

    __shared__ int sh_is64;
    if (tx == 0 && ty == 0) {
        const unsigned int* w = (const unsigned int*)Xi_raw;
        unsigned int acc = 0;
        #pragma unroll
        for (int i = 1; i < 16; i += 2) acc |= w[i];
        sh_is64 = (acc == 0) ? 1 : 0;
    }
    __syncthreads();
    const bool is64 = (sh_is64 != 0);

    float s = 0.f, sq = 0.f;
    #pragma unroll
    for (int f = 0; f < FDIM; ++f) {
        int idx = is64 ? (int)Xi64[(size_t)n * FDIM + f] : Xi32[(size_t)n * FDIM + f];
        float xv = Xv[(size_t)n * FDIM + f];
        float w  = W2[((size_t)f * VDIM + idx) * EDIM + tx] * xv;
        g_deep[(size_t)n * KDEEP + f * EDIM + tx] = __float2half(w);
        s += w; sq += w * w;
    }
    float v = 0.5f * (s * s - sq);
    if (tx < FDIM) {
        int idx = is64 ? (int)Xi64[(size_t)n * FDIM + tx] : Xi32[(size_t)n * FDIM + tx];
        v += W1[(size_t)tx * VDIM + idx] * Xv[(size_t)n * FDIM + tx];
    }
    #pragma unroll
    for (int off = 16; off > 0; off >>= 1) v += __shfl_down_sync(0xffffffffu, v, off);
    __shared__ float red[8][2];
    if ((tx & 31) == 0) red[ty][tx >> 5] = v;
    __syncthreads();
    if (tx == 0) out[n] = red[ty][0] + red[ty][1] + bias[0];
}

// ----------------- 2. weight prep -----------------
__global__ void prep_wt_kernel(const float* __restrict__ W,
                               __half* __restrict__ Bt, int K, int C) {
    __shared__ float t[32][33];
    const int c0 = blockIdx.x * 32, k0 = blockIdx.y * 32;
    #pragma unroll
    for (int r = threadIdx.y; r < 32; r += 8)
        t[r][threadIdx.x] = W[(size_t)(k0 + r) * C + c0 + threadIdx.x];
    __syncthreads();
    #pragma unroll
    for (int r = threadIdx.y; r < 32; r += 8)
        Bt[(size_t)(c0 + r) * K + k0 + threadIdx.x] = __float2half(t[threadIdx.x][r]);
}

// ----------------- 3. FP16 HMMA GEMM + fused BN stats (+optional BN on A) --
#define BM 128
#define BNT 128
#define BKC 64
#define ROWB 128
#define A_BYTES (BM * ROWB)
#define B_BYTES (BNT * ROWB)
#define OFF_A 0
#define OFF_B (A_BYTES)
#define STAGE_BYTES (A_BYTES + B_BYTES)     // 32768
#define NSTAGE 3
#define GEMM_SMEM (NSTAGE * STAGE_BYTES)    // 98304

template<bool BN>
__global__ void __launch_bounds__(128, 2)
gemmh_kernel(const __half* __restrict__ Ag, const __half* __restrict__ Bg,
             const float* __restrict__ bias, __half* __restrict__ Z,
             int K, int Nc, int tiles_n, int ntiles) {
    extern __shared__ __align__(1024) char smem[];
    const uint32_t sb = smem_u32(smem);
    const int tid = threadIdx.x, wid = tid >> 5, lane = tid & 31;
    const int wm = wid & 1, wn = wid >> 1;

    const int r0 = tid >> 3, ch = tid & 7;
    const uint32_t cxor   = ((uint32_t)(ch * 16)) ^ ((uint32_t)(r0 & 7) * 16);
    const uint32_t adst0  = OFF_A + (uint32_t)r0 * ROWB + cxor;
    const uint32_t bdst0  = OFF_B + (uint32_t)r0 * ROWB + cxor;
    const size_t   srcoff = (size_t)r0 * K + ch * 8;
    const size_t   K16    = (size_t)16 * K;

    const uint32_t a_row  = (uint32_t)(wm * 64 + (lane & 15));
    const uint32_t a_colb = (uint32_t)((lane >> 4) * 16);
    const uint32_t b_row  = (uint32_t)(wn * 64 + ((lane >> 4) & 1) * 8 + (lane & 7));
    const uint32_t b_colb = (uint32_t)(((lane >> 3) & 1) * 16);
    uint32_t axor[4], bxor[4];
    #pragma unroll
    for (int ks = 0; ks < 4; ++ks) {
        axor[ks] = ((uint32_t)(ks * 32) + a_colb) ^ ((a_row & 7) * 16);
        bxor[ks] = ((uint32_t)(ks * 32) + b_colb) ^ ((b_row & 7) * 16);
    }
    const uint32_t a_base = OFF_A + a_row * ROWB;
    const uint32_t b_base = OFF_B + b_row * ROWB;
    const int kp0 = lane & 3;

    const __half2* sc2 = (const __half2*)g_sc2;
    const __half2* sh2 = (const __half2*)g_sh2;

    const int nc = K / BKC;

    for (int t = blockIdx.x; t < ntiles; t += gridDim.x) {
        const int bx = t % tiles_n, by = t / tiles_n;
        const int m0 = by * BM, n0 = bx * BNT;
        const __half* asrc = Ag + (size_t)m0 * K + srcoff;
        const __half* bsrc = Bg + (size_t)n0 * K + srcoff;

        float acc[4][8][4];
        #pragma unroll
        for (int i = 0; i < 4; ++i)
            #pragma unroll
            for (int j = 0; j < 8; ++j)
                #pragma unroll
                for (int q = 0; q < 4; ++q) acc[i][j][q] = 0.f;

        #pragma unroll
        for (int s = 0; s < 2; ++s) {
            const uint32_t st = sb + (uint32_t)s * STAGE_BYTES;
            #pragma unroll
            for (int q = 0; q < 8; ++q) {
                CP_ASYNC16(st + adst0 + q * 2048, asrc + s * BKC + q * K16);
                CP_ASYNC16(st + bdst0 + q * 2048, bsrc + s * BKC + q * K16);
            }
            CP_COMMIT();
        }

        uint32_t afr[2][4][4], bfr[2][8][2];

        for (int i = 0; i < nc; ++i) {
            CP_WAIT(1);
            __syncthreads();
            {
                const int j = i + 2;
                if (j < nc) {
                    const uint32_t st = sb + (uint32_t)(j % NSTAGE) * STAGE_BYTES;
                    #pragma unroll
                    for (int q = 0; q < 8; ++q) {
                        CP_ASYNC16(st + adst0 + q * 2048, asrc + j * BKC + q * K16);
                        CP_ASYNC16(st + bdst0 + q * 2048, bsrc + j * BKC + q * K16);
                    }
                }
                CP_COMMIT();
            }
            const uint32_t st = sb + (uint32_t)(i % NSTAGE) * STAGE_BYTES;
            const int kpi = i * 32 + kp0;

            #pragma unroll
            for (int mt = 0; mt < 4; ++mt)
                ldsm_x4(afr[0][mt], st + a_base + mt * 2048 + axor[0]);
            if (BN) {
                const __half2 s0 = sc2[kpi],     h0 = sh2[kpi];
                const __half2 s1 = sc2[kpi + 4], h1 = sh2[kpi + 4];
                #pragma unroll
                for (int mt = 0; mt < 4; ++mt) {
                    afr[0][mt][0] = bnrelu2(afr[0][mt][0], s0, h0);
                    afr[0][mt][1] = bnrelu2(afr[0][mt][1], s0, h0);
                    afr[0][mt][2] = bnrelu2(afr[0][mt][2], s1, h1);
                    afr[0][mt][3] = bnrelu2(afr[0][mt][3], s1, h1);
                }
            }
            #pragma unroll
            for (int p = 0; p < 4; ++p) {
                uint32_t tt[4];
                ldsm_x4(tt, st + b_base + p * 2048 + bxor[0]);
                bfr[0][2*p][0] = tt[0]; bfr[0][2*p][1] = tt[1];
                bfr[0][2*p+1][0] = tt[2]; bfr[0][2*p+1][1] = tt[3];
            }

            #pragma unroll
            for (int ks = 0; ks < 4; ++ks) {
                const int cur = ks & 1, nxt = cur ^ 1;
                if (ks < 3) {
                    #pragma unroll
                    for (int mt = 0; mt < 4; ++mt)
                        ldsm_x4(afr[nxt][mt], st + a_base + mt * 2048 + axor[ks + 1]);
                    if (BN) {
                        const int kp = kpi + (ks + 1) * 8;
                        const __half2 s0 = sc2[kp],     h0 = sh2[kp];
                        const __half2 s1 = sc2[kp + 4], h1 = sh2[kp + 4];
                        #pragma unroll
                        for (int mt = 0; mt < 4; ++mt) {
                            afr[nxt][mt][0] = bnrelu2(afr[nxt][mt][0], s0, h0);
                            afr[nxt][mt][1] = bnrelu2(afr[nxt][mt][1], s0, h0);
                            afr[nxt][mt][2] = bnrelu2(afr[nxt][mt][2], s1, h1);
                            afr[nxt][mt][3] = bnrelu2(afr[nxt][mt][3], s1, h1);
                        }
                    }
                    #pragma unroll
                    for (int p = 0; p < 4; ++p) {
                        uint32_t tt[4];
                        ldsm_x4(tt, st + b_base + p * 2048 + bxor[ks + 1]);
                        bfr[nxt][2*p][0] = tt[0]; bfr[nxt][2*p][1] = tt[1];
                        bfr[nxt][2*p+1][0] = tt[2]; bfr[nxt][2*p+1][1] = tt[3];
                    }
                }
                #pragma unroll
                for (int mt = 0; mt < 4; ++mt)
                    #pragma unroll
                    for (int nt = 0; nt < 8; ++nt)
                        mma_f16(acc[mt][nt], afr[cur][mt], bfr[cur][nt]);
            }
        }

        // ---------- epilogue: fp16 z + per-tile BN partial stats ----------
        __syncthreads();
        float* colsum = (float*)smem;
        float* colsq  = (float*)smem + 128;
        colsum[tid] = 0.f; colsq[tid] = 0.f;
        __syncthreads();

        #pragma unroll
        for (int nt = 0; nt < 8; ++nt) {
            const int cloc = wn * 64 + nt * 8 + (lane & 3) * 2;
            const int col  = n0 + cloc;
            const float b0 = bias[col], b1 = bias[col + 1];
            float s0 = 0.f, s1 = 0.f, q0 = 0.f, q1 = 0.f;
            #pragma unroll
            for (int mt = 0; mt < 4; ++mt) {
                const int row = m0 + wm * 64 + mt * 16 + (lane >> 2);
                float z00 = acc[mt][nt][0] + b0, z01 = acc[mt][nt][1] + b1;
                float z10 = acc[mt][nt][2] + b0, z11 = acc[mt][nt][3] + b1;
                s0 += z00 + z10;  s1 += z01 + z11;
                q0 += z00 * z00 + z10 * z10;  q1 += z01 * z01 + z11 * z11;
                *(uint32_t*)&Z[(size_t)row * Nc + col]       = pack2h(__float2half(z00), __float2half(z01));
                *(uint32_t*)&Z[(size_t)(row + 8) * Nc + col] = pack2h(__float2half(z10), __float2half(z11));
            }
            #pragma unroll
            for (int off = 16; off >= 4; off >>= 1) {
                s0 += __shfl_down_sync(0xffffffffu, s0, off);
                s1 += __shfl_down_sync(0xffffffffu, s1, off);
                q0 += __shfl_down_sync(0xffffffffu, q0, off);
                q1 += __shfl_down_sync(0xffffffffu, q1, off);
            }
            if ((lane >> 2) == 0) {
                atomicAdd(&colsum[cloc], s0);     atomicAdd(&colsum[cloc + 1], s1);
                atomicAdd(&colsq[cloc],  q0);     atomicAdd(&colsq[cloc + 1],  q1);
            }
        }
        __syncthreads();
        g_psumf[(size_t)by * Nc + n0 + tid] = colsum[tid];
        g_psqf [(size_t)by * Nc + n0 + tid] = colsq[tid];
        __syncthreads();
    }
}

// ----------------- 4. BN finalize: 1 block per column, 128-thread tree -----
__global__ void bn_finalize_kernel(const float* __restrict__ g,
                                   const float* __restrict__ b, int C) {
    const int col = blockIdx.x;
    const int t   = threadIdx.x;          // 0..127 = partial index
    double s  = (double)g_psumf[(size_t)t * C + col];
    double ss = (double)g_psqf [(size_t)t * C + col];
    // warp tree
    #pragma unroll
    for (int off = 16; off > 0; off >>= 1) {
        s  += __shfl_down_sync(0xffffffffu, s,  off);
        ss += __shfl_down_sync(0xffffffffu, ss, off);
    }
    __shared__ double sh_s[4], sh_q[4];
    if ((t & 31) == 0) { sh_s[t >> 5] = s; sh_q[t >> 5] = ss; }
    __syncthreads();
    if (t == 0) {
        s  = sh_s[0] + sh_s[1] + sh_s[2] + sh_s[3];
        ss = sh_q[0] + sh_q[1] + sh_q[2] + sh_q[3];
        double mean = s / (double)NROWS;
        double var  = ss / (double)NROWS - mean * mean;
        float sc = g[col] * rsqrtf((float)var + BN_EPS);
        float sh = b[col] - (float)mean * sc;
        g_scale[col] = sc;
        g_shift[col] = sh;
        g_sc2[col] = __float2half(sc);
        g_sh2[col] = __float2half(sh);
    }
}

// ----------------- 5. fused layer-3 BN + ReLU + row-sum -----------------
__global__ void rowsum_bn_kernel(const __half* __restrict__ z, float* __restrict__ out) {
    const int gwarp = (blockIdx.x * blockDim.x + threadIdx.x) >> 5;
    const int lane  = threadIdx.x & 31;
    if (gwarp >= NROWS) return;
    const __half2* p = (const __half2*)(z + (size_t)gwarp * C3);
    float s = 0.f;
    #pragma unroll
    for (int j = 0; j < C3 / 64; ++j) {
        const int c2 = lane + j * 32;
        float2 v = __half22float2(p[c2]);
        s += fmaxf(fmaf(v.x, g_scale[2 * c2], g_shift[2 * c2]), 0.f);
        s += fmaxf(fmaf(v.y, g_scale[2 * c2 + 1], g_shift[2 * c2 + 1]), 0.f);
    }
    #pragma unroll
    for (int off = 16; off > 0; off >>= 1) s += __shfl_down_sync(0xffffffffu, s, off);
    if (lane == 0) out[gwarp] += s;
}

// ---------------------------------------------------------------------------
extern "C" void kernel_launch(void* const* d_in, const int* in_sizes, int n_in,
                              void* d_out, int out_size) {
    const void*  Xi   = d_in[0];
    const float* Xv   = (const float*)d_in[1];
    const float* W1   = (const float*)d_in[2];
    const float* W2   = (const float*)d_in[3];
    const float* bias = (const float*)d_in[4];
    const float* lw1  = (const float*)d_in[5];
    const float* lb1  = (const float*)d_in[6];
    const float* g1   = (const float*)d_in[7];
    const float* b1   = (const float*)d_in[8];
    const float* lw2  = (const float*)d_in[9];
    const float* lb2  = (const float*)d_in[10];
    const float* g2   = (const float*)d_in[11];
    const float* b2   = (const float*)d_in[12];
    const float* lw3  = (const float*)d_in[13];
    const float* lb3  = (const float*)d_in[14];
    const float* g3   = (const float*)d_in[15];
    const float* b3   = (const float*)d_in[16];
    float* out = (float*)d_out;

    __half *deep, *zA, *zB, *bt1, *bt2, *bt3;
    cudaGetSymbolAddress((void**)&deep, g_deep);
    cudaGetSymbolAddress((void**)&zA,   g_zA);
    cudaGetSymbolAddress((void**)&zB,   g_zB);
    cudaGetSymbolAddress((void**)&bt1,  g_bt1);
    cudaGetSymbolAddress((void**)&bt2,  g_bt2);
    cudaGetSymbolAddress((void**)&bt3,  g_bt3);

    static int nsm = 0;
    static cudaStream_t s2;
    static cudaEvent_t evFork, evJoin;
    if (nsm == 0) {
        cudaDeviceGetAttribute(&nsm, cudaDevAttrMultiProcessorCount, 0);
        if (nsm <= 0) nsm = 148;
        cudaFuncSetAttribute(gemmh_kernel<false>, cudaFuncAttributeMaxDynamicSharedMemorySize, GEMM_SMEM);
        cudaFuncSetAttribute(gemmh_kernel<true>,  cudaFuncAttributeMaxDynamicSharedMemorySize, GEMM_SMEM);
        cudaStreamCreateWithFlags(&s2, cudaStreamNonBlocking);
        cudaEventCreateWithFlags(&evFork, cudaEventDisableTiming);
        cudaEventCreateWithFlags(&evJoin, cudaEventDisableTiming);
    }
    const int P = 2 * nsm;

    // ---- fork: weight preps overlapped with embed ----
    cudaEventRecord(evFork, 0);
    cudaStreamWaitEvent(s2, evFork, 0);
    prep_wt_kernel<<<dim3(C1 / 32, KDEEP / 32), dim3(32, 8), 0, s2>>>(lw1, bt1, KDEEP, C1);
    prep_wt_kernel<<<dim3(C2 / 32, C1 / 32),    dim3(32, 8), 0, s2>>>(lw2, bt2, C1, C2);
    prep_wt_kernel<<<dim3(C3 / 32, C2 / 32),    dim3(32, 8), 0, s2>>>(lw3, bt3, C2, C3);
    cudaEventRecord(evJoin, s2);

    dim3 ebt(64, 8);
    embed_kernel<<<NROWS / 8, ebt>>>(Xi, Xv, W1, W2, bias, out);

    cudaStreamWaitEvent(0, evJoin, 0);

    // ---- layer 1: 2496 -> 1024 ----
    {
        const int tn = C1 / BNT, nt = tn * (NROWS / BM);
        gemmh_kernel<false><<<nt, 128, GEMM_SMEM>>>(deep, bt1, lb1, zA, KDEEP, C1, tn, nt);
        bn_finalize_kernel<<<C1, 128>>>(g1, b1, C1);
    }
    // ---- layer 2: 1024 -> 512 ----
    {
        const int tn = C2 / BNT, nt = tn * (NROWS / BM);
        gemmh_kernel<true><<<(nt < P ? nt : P), 128, GEMM_SMEM>>>(zA, bt2, lb2, zB, C1, C2, tn, nt);
        bn_finalize_kernel<<<C2, 128>>>(g2, b2, C2);
    }
    // ---- layer 3: 512 -> 256 ----
    {
        const int tn = C3 / BNT, nt = tn * (NROWS / BM);
        gemmh_kernel<true><<<(nt < P ? nt : P), 128, GEMM_SMEM>>>(zB, bt3, lb3, zA, C2, C3, tn, nt);
        bn_finalize_kernel<<<C3, 128>>>(g3, b3, C3);
    }
    rowsum_bn_kernel<<<(NROWS * 32 + 255) / 256, 256>>>(zA, out);
}